// round 14
// baseline (speedup 1.0000x reference)
#include <cuda_runtime.h>
#include <cuda_fp16.h>
#include <math.h>
#include <stdint.h>

// Problem constants (B=1)
#define S     1024
#define H     32
#define HKV   8
#define D     128
#define HID   4096
#define KVHID 1024
#define QKVW  (HID + 2 * KVHID)   // 6144
#define GROUPS 4

// ---------------- scratch (static device globals: no allocs allowed) -------
__device__ __half g_hs_hi[(size_t)S * HID];
__device__ __half g_wqkv_hi[(size_t)QKVW * HID];
__device__ __half g_wo_hi[(size_t)HID * HID];
__device__ __half g_q_hi[(size_t)S * HID];
__device__ __half g_k_hi[(size_t)S * KVHID];
__device__ __half g_vT_hi[(size_t)KVHID * S];
__device__ __half g_ctx_hi[(size_t)S * HID];

// ---------------- helpers ---------------------------------------------------
__device__ __forceinline__ void mma16816(float* c, const uint32_t* a, const uint32_t* b) {
    asm volatile(
        "mma.sync.aligned.m16n8k16.row.col.f32.f16.f16.f32 "
        "{%0,%1,%2,%3}, {%4,%5,%6,%7}, {%8,%9}, {%0,%1,%2,%3};"
        : "+f"(c[0]), "+f"(c[1]), "+f"(c[2]), "+f"(c[3])
        : "r"(a[0]), "r"(a[1]), "r"(a[2]), "r"(a[3]), "r"(b[0]), "r"(b[1]));
}

__device__ __forceinline__ void ldsm4(uint32_t* r, uint32_t addr) {
    asm volatile("ldmatrix.sync.aligned.m8n8.x4.shared.b16 {%0,%1,%2,%3}, [%4];"
        : "=r"(r[0]), "=r"(r[1]), "=r"(r[2]), "=r"(r[3]) : "r"(addr));
}

__device__ __forceinline__ void cp_async16(uint32_t smem_addr, const void* gptr) {
    asm volatile("cp.async.cg.shared.global [%0], [%1], 16;"
                 :: "r"(smem_addr), "l"(gptr));
}
__device__ __forceinline__ void cp_commit() {
    asm volatile("cp.async.commit_group;" ::: "memory");
}
template <int N>
__device__ __forceinline__ void cp_wait() {
    asm volatile("cp.async.wait_group %0;" :: "n"(N) : "memory");
}

__device__ __forceinline__ uint32_t smem_u32(const void* p) {
    uint32_t a;
    asm("{ .reg .u64 t; cvta.to.shared.u64 t, %1; cvt.u32.u64 %0, t; }"
        : "=r"(a) : "l"(p));
    return a;
}

__device__ __forceinline__ uint32_t packh2(float a, float b) {
    __half2 h = __halves2half2(__float2half(a), __float2half(b));
    return *(uint32_t*)&h;
}

// 64B-row swizzle (flash attention tiles)
__device__ __forceinline__ uint32_t swoff(uint32_t r, uint32_t c) {
    return r * 64u + (((c ^ (r >> 1)) & 3u) << 4);
}
// 128B-row swizzle (GEMM BK=64 tiles): chunk c in 0..7
__device__ __forceinline__ uint32_t sw128(uint32_t r, uint32_t c) {
    return r * 128u + (((c ^ (r & 7u)) & 7u) << 4);
}

// ====== NT GEMM 128x128 tile, BK=64: single-product fp16 HMMA, 2 CTAs/SM ===
#define ARRB  16384            // 128 rows * 128 B
#define STGB  (2 * ARRB)       // Ahi|Bhi = 32768 B
#define STAGES 3
#define GSMEM (STAGES * STGB)  // 98304 B
#define FT_STRIDE 132          // padded fp32 tile row stride (floats)

template <bool QKV_EPI>
__global__ void __launch_bounds__(256, 2) gemm_fp16(
    const __half* __restrict__ Ahi, const __half* __restrict__ Bhi,
    float* __restrict__ C, int K, int lda, int ldb, int ldc,
    const int* __restrict__ pos, const float* __restrict__ prior,
    __half* __restrict__ qhi, __half* __restrict__ khi,
    __half* __restrict__ vthi, int bx_base)
{
    extern __shared__ char smem[];
    const uint32_t smem_b = smem_u32(smem);
    const int tid = threadIdx.x;
    const int wid = tid >> 5;
    const int lane = tid & 31;
    const int g  = lane >> 2;
    const int tc = lane & 3;
    const int warp_m = wid & 3;
    const int warp_n = wid >> 2;
    const int KT = K / 64;

    Ahi += (size_t)blockIdx.y * 128 * lda;
    Bhi += (size_t)blockIdx.x * 128 * ldb;

    const int lr0 = tid >> 3;
    const int lc0 = tid & 7;
    const uint32_t stsOff[4] = {
        sw128(lr0,      lc0), sw128(lr0 + 32, lc0),
        sw128(lr0 + 64, lc0), sw128(lr0 + 96, lc0)
    };

    const uint32_t aRow0 = warp_m * 32 + ((lane >> 3) & 1) * 8 + (lane & 7);
    const uint32_t aSel  = (uint32_t)lane >> 4;
    const uint32_t bSel  = ((uint32_t)lane >> 3) & 1;
    const uint32_t bRowB = warp_n * 64 + ((lane >> 4) & 1) * 8 + (lane & 7);

    float acc[2][8][4];
#pragma unroll
    for (int i = 0; i < 2; i++)
#pragma unroll
        for (int j = 0; j < 8; j++)
#pragma unroll
            for (int e = 0; e < 4; e++) acc[i][j][e] = 0.0f;

    auto issue_stage = [&](int kt, int s) {
        const uint32_t sb = smem_b + s * STGB;
        int kk = kt * 64;
#pragma unroll
        for (int t = 0; t < 4; t++) {
            int r = lr0 + t * 32;
            cp_async16(sb + stsOff[t],        Ahi + (size_t)r * lda + kk + lc0 * 8);
            cp_async16(sb + ARRB + stsOff[t], Bhi + (size_t)r * ldb + kk + lc0 * 8);
        }
    };

#pragma unroll
    for (int p = 0; p < STAGES - 1; p++) {
        if (p < KT) issue_stage(p, p);
        cp_commit();
    }

    int s = 0;
    for (int kt = 0; kt < KT; kt++) {
        cp_wait<STAGES - 2>();
        __syncthreads();

        int nk = kt + STAGES - 1;
        int ns = s + STAGES - 1; if (ns >= STAGES) ns -= STAGES;
        if (nk < KT) issue_stage(nk, ns);
        cp_commit();

        const uint32_t sa_hi = smem_b + s * STGB;
        const uint32_t sb_hi = sa_hi + ARRB;

#pragma unroll
        for (int ks = 0; ks < 4; ks++) {
            const uint32_t ac = ks * 2 + aSel;
            uint32_t AH[2][4];
#pragma unroll
            for (int mt = 0; mt < 2; mt++)
                ldsm4(AH[mt], sa_hi + sw128(aRow0 + mt * 16, ac));
            const uint32_t bc = ks * 2 + bSel;
#pragma unroll
            for (int p = 0; p < 4; p++) {
                uint32_t BH[4];
                ldsm4(BH, sb_hi + sw128(bRowB + p * 16, bc));
#pragma unroll
                for (int mt = 0; mt < 2; mt++)
#pragma unroll
                    for (int q = 0; q < 2; q++)
                        mma16816(acc[mt][2 * p + q], AH[mt], BH + 2 * q);
            }
        }
        if (++s == STAGES) s = 0;
    }

    if (!QKV_EPI) {
        const int rowb = blockIdx.y * 128 + warp_m * 32;
        const int colb = blockIdx.x * 128 + warp_n * 64;
#pragma unroll
        for (int mt = 0; mt < 2; mt++)
#pragma unroll
            for (int nt = 0; nt < 8; nt++) {
                int rr = rowb + mt * 16 + g;
                int cc = colb + nt * 8 + tc * 2;
                *(float2*)(C + (size_t)rr * ldc + cc) =
                    make_float2(acc[mt][nt][0], acc[mt][nt][1]);
                *(float2*)(C + (size_t)(rr + 8) * ldc + cc) =
                    make_float2(acc[mt][nt][2], acc[mt][nt][3]);
            }
        return;
    }

    // ================= fused QKV projection epilogue =================
    __syncthreads();
    float* ft     = (float*)smem;                            // 128 x 132 fp32
    float* eta_sm = (float*)(smem + 128 * FT_STRIDE * 4);    // 128 floats

    const int s0 = blockIdx.y * 128;
#pragma unroll
    for (int mt = 0; mt < 2; mt++)
#pragma unroll
        for (int nt = 0; nt < 8; nt++) {
            int rr = warp_m * 32 + mt * 16 + g;
            int cc = warp_n * 64 + nt * 8 + tc * 2;
            *(float2*)(ft + rr * FT_STRIDE + cc) =
                make_float2(acc[mt][nt][0], acc[mt][nt][1]);
            *(float2*)(ft + (rr + 8) * FT_STRIDE + cc) =
                make_float2(acc[mt][nt][2], acc[mt][nt][3]);
        }
    if (tid < 128) {
        float pr = prior[s0 + tid];
        eta_sm[tid] = fminf(fmaxf(1.0f + 0.5f * pr, 0.5f), 2.0f);  // gamma==eta
    }
    __syncthreads();

    const int bx = blockIdx.x + bx_base;
    if (bx < 40) {
        // RoPE path (q: bx 0..31, k: bx 32..39)
        const int r  = tid >> 1;            // row 0..127
        const int dh = (tid & 1) << 5;      // 0 / 32
        const int ss = s0 + r;
        const float p = (float)pos[ss];
        const float scale = (bx < 32) ? 0.08838834764831845f : eta_sm[r];

        uint32_t w1[16], w2[16];
#pragma unroll
        for (int jv = 0; jv < 8; jv++) {
            float4 X1 = *(const float4*)(ft + r * FT_STRIDE + dh + jv * 4);
            float4 X2 = *(const float4*)(ft + r * FT_STRIDE + dh + 64 + jv * 4);
            float y1[4], y2[4];
            const float* x1 = (const float*)&X1;
            const float* x2 = (const float*)&X2;
#pragma unroll
            for (int e = 0; e < 4; e++) {
                int d = dh + jv * 4 + e;
                float inv = exp2f(-0.2076245760856056f * (float)d);
                float sn, cs;
                sincosf(p * inv, &sn, &cs);
                y1[e] = (x1[e] * cs - x2[e] * sn) * scale;
                y2[e] = (x2[e] * cs + x1[e] * sn) * scale;
            }
            w1[jv * 2]     = packh2(y1[0], y1[1]);
            w1[jv * 2 + 1] = packh2(y1[2], y1[3]);
            w2[jv * 2]     = packh2(y2[0], y2[1]);
            w2[jv * 2 + 1] = packh2(y2[2], y2[3]);
        }
        __half* dst = (bx < 32)
            ? qhi + (size_t)ss * HID + bx * 128
            : khi + (size_t)ss * KVHID + (bx - 32) * 128;
#pragma unroll
        for (int k4 = 0; k4 < 4; k4++) {
            *(uint4*)(dst + dh + k4 * 8) =
                make_uint4(w1[k4 * 4], w1[k4 * 4 + 1], w1[k4 * 4 + 2], w1[k4 * 4 + 3]);
            *(uint4*)(dst + dh + 64 + k4 * 8) =
                make_uint4(w2[k4 * 4], w2[k4 * 4 + 1], w2[k4 * 4 + 2], w2[k4 * 4 + 3]);
        }
    } else {
        // V path: eta scale + transpose -> vThi[(hv*128+cc)*S + s]
        const int hv = bx - 40;
#pragma unroll
        for (int ci = 0; ci < 16; ci++) {
            int cc = wid * 16 + ci;
            size_t base = (size_t)(hv * 128 + cc) * S + s0;
#pragma unroll
            for (int q2 = 0; q2 < 4; q2++) {
                int r = lane + 32 * q2;
                vthi[base + r] = __float2half(ft[r * FT_STRIDE + cc] * eta_sm[r]);
            }
        }
    }
}

// ======================= fused flash attention ==============================
#define FA_QHI   0
#define FA_BIAS  32768
#define FA_U     36864
#define FA_KV0   40960
#define FA_KSTG  65536
#define FA_SMEM  (FA_KV0 + 2 * FA_KSTG)   // 172032

__global__ void __launch_bounds__(256, 1) flash_attn(
    const __half* __restrict__ qhi,
    const __half* __restrict__ khi, const __half* __restrict__ vthi,
    const float* __restrict__ prior, const float* __restrict__ m1,
    const float* __restrict__ m2,
    __half* __restrict__ cxhi)
{
    const int h    = blockIdx.x;
    const int by   = 7 - (int)blockIdx.y;
    const int hk   = h >> 2;
    const int nblk = by + 1;

    extern __shared__ char smem[];
    const uint32_t sb = smem_u32(smem);
    const int tid = threadIdx.x;
    const int wid = tid >> 5;
    const int lane = tid & 31;
    const int g = lane >> 2, tc = lane & 3;

    const float l1 = m1[h], l2 = m2[h];

    float* biasb = (float*)(smem + FA_BIAS);
    float* ub    = (float*)(smem + FA_U);
    for (int j = tid; j < S; j += 256) {
        float pj = prior[j];
        biasb[j] = fminf(fmaxf(pj, -5.0f), 5.0f) * l1;
        ub[j]    = 1.0f + 0.5f * pj * l2;
    }

    {
        const __half* qh = qhi + (size_t)(by * 128) * HID + h * D;
#pragma unroll
        for (int t = 0; t < 8; t++) {
            int id = tid + t * 256;
            int r = id >> 4, cc = id & 15;
            uint32_t dst = (uint32_t)(cc >> 2) * 8192 + swoff(r, cc & 3);
            cp_async16(sb + FA_QHI + dst, qh + (size_t)r * HID + cc * 8);
        }
    }

    auto issue_kv = [&](int j, int st) {
        const uint32_t kb = sb + FA_KV0 + st * FA_KSTG;
        const __half* kp = khi  + (size_t)(j * 128) * KVHID + hk * D;
        const __half* vp = vthi + (size_t)(hk * 128) * S + j * 128;
#pragma unroll
        for (int t = 0; t < 8; t++) {
            int id = tid + t * 256;
            int r = id >> 4, cc = id & 15;
            uint32_t dst = (uint32_t)(cc >> 2) * 8192 + swoff(r, cc & 3);
            cp_async16(kb + dst,         kp + (size_t)r * KVHID + cc * 8);
            cp_async16(kb + 32768 + dst, vp + (size_t)r * S + cc * 8);
        }
    };

    issue_kv(0, 0);
    cp_commit();

    const uint32_t aRowQ = wid * 16 + ((lane >> 3) & 1) * 8 + (lane & 7);
    const uint32_t aSel  = (uint32_t)lane >> 4;
    const uint32_t bSel  = ((uint32_t)lane >> 3) & 1;
    const uint32_t bRow  = ((lane >> 4) & 1) * 8 + (lane & 7);

    float oacc[16][4];
#pragma unroll
    for (int i = 0; i < 16; i++)
#pragma unroll
        for (int e = 0; e < 4; e++) oacc[i][e] = 0.0f;
    float mrun0 = -1e30f, mrun1 = -1e30f;
    float srun0 = 0.0f,   srun1 = 0.0f;

    const int row0 = wid * 16 + g;

    for (int j = 0; j < nblk; j++) {
        const int st = j & 1;
        if (j + 1 < nblk) { issue_kv(j + 1, st ^ 1); cp_commit(); cp_wait<1>(); }
        else              { cp_wait<0>(); }
        __syncthreads();

        const uint32_t kb = sb + FA_KV0 + st * FA_KSTG;
        const uint32_t vb = kb + 32768;

        float sacc[16][4];
#pragma unroll
        for (int i = 0; i < 16; i++)
#pragma unroll
            for (int e = 0; e < 4; e++) sacc[i][e] = 0.0f;

#pragma unroll
        for (int kf = 0; kf < 8; kf++) {
            uint32_t sub = (uint32_t)(kf >> 1) * 8192;
            uint32_t kc  = (uint32_t)(kf & 1) * 2;
            uint32_t AH[4];
            ldsm4(AH, sb + FA_QHI + sub + swoff(aRowQ, kc + aSel));
#pragma unroll
            for (int p = 0; p < 8; p++) {
                uint32_t BH[4];
                ldsm4(BH, kb + sub + swoff(bRow + p * 16, kc + bSel));
#pragma unroll
                for (int q = 0; q < 2; q++)
                    mma16816(sacc[2 * p + q], AH, BH + 2 * q);
            }
        }

        const float* bias = biasb + j * 128;
        const float* uu   = ub + j * 128;
        const bool diag = (j == by);

        float mb0 = -1e30f, mb1 = -1e30f;
#pragma unroll
        for (int nt = 0; nt < 16; nt++) {
            int k0 = nt * 8 + tc * 2;
            float b0 = bias[k0], b1 = bias[k0 + 1];
            float a0 = sacc[nt][0] + b0;
            float a1 = sacc[nt][1] + b1;
            float a2 = sacc[nt][2] + b0;
            float a3 = sacc[nt][3] + b1;
            if (diag) {
                if (k0     > row0)     a0 = -1e30f;
                if (k0 + 1 > row0)     a1 = -1e30f;
                if (k0     > row0 + 8) a2 = -1e30f;
                if (k0 + 1 > row0 + 8) a3 = -1e30f;
            }
            sacc[nt][0] = a0; sacc[nt][1] = a1;
            sacc[nt][2] = a2; sacc[nt][3] = a3;
            mb0 = fmaxf(mb0, fmaxf(a0, a1));
            mb1 = fmaxf(mb1, fmaxf(a2, a3));
        }
        mb0 = fmaxf(mb0, __shfl_xor_sync(0xffffffffu, mb0, 1));
        mb0 = fmaxf(mb0, __shfl_xor_sync(0xffffffffu, mb0, 2));
        mb1 = fmaxf(mb1, __shfl_xor_sync(0xffffffffu, mb1, 1));
        mb1 = fmaxf(mb1, __shfl_xor_sync(0xffffffffu, mb1, 2));

        float mn0 = fmaxf(mrun0, mb0);
        float mn1 = fmaxf(mrun1, mb1);
        float sc0 = __expf(mrun0 - mn0);
        float sc1 = __expf(mrun1 - mn1);
        mrun0 = mn0; mrun1 = mn1;

        float rs0 = 0.0f, rs1 = 0.0f;
#pragma unroll
        for (int nt = 0; nt < 16; nt++) {
            int k0 = nt * 8 + tc * 2;
            float u0 = uu[k0], u1 = uu[k0 + 1];
            float e0 = __expf(sacc[nt][0] - mn0) * u0;
            float e1 = __expf(sacc[nt][1] - mn0) * u1;
            float e2 = __expf(sacc[nt][2] - mn1) * u0;
            float e3 = __expf(sacc[nt][3] - mn1) * u1;
            sacc[nt][0] = e0; sacc[nt][1] = e1;
            sacc[nt][2] = e2; sacc[nt][3] = e3;
            rs0 += e0 + e1; rs1 += e2 + e3;
            oacc[nt][0] *= sc0; oacc[nt][1] *= sc0;
            oacc[nt][2] *= sc1; oacc[nt][3] *= sc1;
        }
        rs0 += __shfl_xor_sync(0xffffffffu, rs0, 1);
        rs0 += __shfl_xor_sync(0xffffffffu, rs0, 2);
        rs1 += __shfl_xor_sync(0xffffffffu, rs1, 1);
        rs1 += __shfl_xor_sync(0xffffffffu, rs1, 2);
        srun0 = srun0 * sc0 + rs0;
        srun1 = srun1 * sc1 + rs1;

#pragma unroll
        for (int kf = 0; kf < 8; kf++) {
            uint32_t AP[4];
            AP[0] = packh2(sacc[2 * kf][0],     sacc[2 * kf][1]);
            AP[1] = packh2(sacc[2 * kf][2],     sacc[2 * kf][3]);
            AP[2] = packh2(sacc[2 * kf + 1][0], sacc[2 * kf + 1][1]);
            AP[3] = packh2(sacc[2 * kf + 1][2], sacc[2 * kf + 1][3]);
            uint32_t sub = (uint32_t)(kf >> 1) * 8192;
            uint32_t kc  = (uint32_t)(kf & 1) * 2;
#pragma unroll
            for (int p = 0; p < 8; p++) {
                uint32_t BV[4];
                ldsm4(BV, vb + sub + swoff(bRow + p * 16, kc + bSel));
                mma16816(oacc[2 * p],     AP, BV);
                mma16816(oacc[2 * p + 1], AP, BV + 2);
            }
        }
        __syncthreads();
    }

    float inv0 = 1.0f / srun0;
    float inv1 = 1.0f / srun1;
    int grow = by * 128 + wid * 16 + g;
    __half* Hp = cxhi + (size_t)grow * HID + h * D + tc * 2;
#pragma unroll
    for (int nt = 0; nt < 16; nt++) {
        *(__half2*)(Hp + nt * 8) =
            __halves2half2(__float2half(oacc[nt][0] * inv0),
                           __float2half(oacc[nt][1] * inv0));
        *(__half2*)(Hp + (size_t)8 * HID + nt * 8) =
            __halves2half2(__float2half(oacc[nt][2] * inv1),
                           __float2half(oacc[nt][3] * inv1));
    }
}

// ---------------- generic fp32 -> fp16 convert ------------------------------
__global__ void cvt_kernel(const float4* __restrict__ src,
                           uint2* __restrict__ dst, int n4)
{
    int stride = gridDim.x * blockDim.x;
    for (int i = blockIdx.x * blockDim.x + threadIdx.x; i < n4; i += stride) {
        float4 v = src[i];
        __half2 a = __floats2half2_rn(v.x, v.y);
        __half2 b = __floats2half2_rn(v.z, v.w);
        uint2 w;
        w.x = *(uint32_t*)&a;
        w.y = *(uint32_t*)&b;
        dst[i] = w;
    }
}

// ---------------- launch ----------------------------------------------------
extern "C" void kernel_launch(void* const* d_in, const int* in_sizes, int n_in,
                              void* d_out, int out_size)
{
    const float* hs    = (const float*)d_in[0];
    const int*   pos   = (const int*)  d_in[2];
    const float* Wq    = (const float*)d_in[3];
    const float* Wk    = (const float*)d_in[4];
    const float* Wv    = (const float*)d_in[5];
    const float* Wo    = (const float*)d_in[6];
    const float* prior = (const float*)d_in[7];
    const float* m1    = (const float*)d_in[8];
    const float* m2    = (const float*)d_in[9];
    float* out = (float*)d_out;

    __half *hshi, *wqkvhi, *wohi, *qhi, *khi, *vthi, *cxhi;
    cudaGetSymbolAddress((void**)&hshi,  g_hs_hi);
    cudaGetSymbolAddress((void**)&wqkvhi,g_wqkv_hi);
    cudaGetSymbolAddress((void**)&wohi,  g_wo_hi);
    cudaGetSymbolAddress((void**)&qhi,   g_q_hi);
    cudaGetSymbolAddress((void**)&khi,   g_k_hi);
    cudaGetSymbolAddress((void**)&vthi,  g_vT_hi);
    cudaGetSymbolAddress((void**)&cxhi,  g_ctx_hi);

    static cudaStream_t s1 = nullptr;
    static cudaEvent_t evA = nullptr, evQ = nullptr, evO = nullptr;
    static int configured = 0;
    if (!configured) {
        cudaFuncSetAttribute(gemm_fp16<true>,
            cudaFuncAttributeMaxDynamicSharedMemorySize, GSMEM);
        cudaFuncSetAttribute(gemm_fp16<false>,
            cudaFuncAttributeMaxDynamicSharedMemorySize, GSMEM);
        cudaFuncSetAttribute(flash_attn,
            cudaFuncAttributeMaxDynamicSharedMemorySize, FA_SMEM);
        cudaStreamCreateWithFlags(&s1, cudaStreamNonBlocking);
        cudaEventCreateWithFlags(&evA, cudaEventDisableTiming);
        cudaEventCreateWithFlags(&evQ, cudaEventDisableTiming);
        cudaEventCreateWithFlags(&evO, cudaEventDisableTiming);
        configured = 1;
    }

    dim3 blk(256);

    // 0a) stream0: convert hs, Wk, Wv (needed by the KV projection part)
    cvt_kernel<<<1024, 256>>>((const float4*)hs, (uint2*)hshi, S * HID / 4);
    cvt_kernel<<<1024, 256>>>((const float4*)Wk,
        (uint2*)(wqkvhi + (size_t)HID * HID), KVHID * HID / 4);
    cvt_kernel<<<1024, 256>>>((const float4*)Wv,
        (uint2*)(wqkvhi + (size_t)(HID + KVHID) * HID), KVHID * HID / 4);
    cudaEventRecord(evA, 0);

    // 0b) stream1 (after cvt A): convert Wq then Wo, overlapping compute below
    cudaStreamWaitEvent(s1, evA, 0);
    cvt_kernel<<<1024, 256, 0, s1>>>((const float4*)Wq, (uint2*)wqkvhi,
                                     HID * HID / 4);
    cudaEventRecord(evQ, s1);
    cvt_kernel<<<1024, 256, 0, s1>>>((const float4*)Wo, (uint2*)wohi,
                                     HID * HID / 4);
    cudaEventRecord(evO, s1);

    // 1a) KV projection part (bx 32..47), runs while Wq converts on s1
    gemm_fp16<true><<<dim3(16, S / 128), blk, GSMEM>>>(
        hshi, wqkvhi + (size_t)32 * 128 * HID, nullptr, HID, HID, HID, 0,
        pos, prior, qhi, khi, vthi, 32);

    // 1b) Q projection part (bx 0..31), gated on Wq conversion
    cudaStreamWaitEvent(0, evQ, 0);
    gemm_fp16<true><<<dim3(32, S / 128), blk, GSMEM>>>(
        hshi, wqkvhi, nullptr, HID, HID, HID, 0,
        pos, prior, qhi, khi, vthi, 0);

    // 2) fused flash attention -> ctx fp16 (Wo cvt still running on s1)
    flash_attn<<<dim3(H, S / 128), blk, FA_SMEM>>>(
        qhi, khi, vthi, prior, m1, m2, cxhi);

    // 3) out = ctx @ Wo^T, gated on Wo conversion
    cudaStreamWaitEvent(0, evO, 0);
    gemm_fp16<false><<<dim3(HID / 128, S / 128), blk, GSMEM>>>(
        cxhi, wohi, out, HID, HID, HID, HID,
        nullptr, nullptr, nullptr, nullptr, nullptr, 0);
}

// round 16
// speedup vs baseline: 1.1179x; 1.1179x over previous
#include <cuda_runtime.h>
#include <cuda_fp16.h>
#include <math.h>
#include <stdint.h>

// Problem constants (B=1)
#define S     1024
#define H     32
#define HKV   8
#define D     128
#define HID   4096
#define KVHID 1024
#define QKVW  (HID + 2 * KVHID)   // 6144
#define GROUPS 4

// ---------------- scratch (static device globals: no allocs allowed) -------
__device__ __half g_hs_hi[(size_t)S * HID];
__device__ __half g_wqkv_hi[(size_t)QKVW * HID];
__device__ __half g_wo_hi[(size_t)HID * HID];
__device__ __half g_q_hi[(size_t)S * HID];
__device__ __half g_k_hi[(size_t)S * KVHID];
__device__ __half g_vT_hi[(size_t)KVHID * S];
__device__ __half g_ctx_hi[(size_t)S * HID];

// ---------------- helpers ---------------------------------------------------
__device__ __forceinline__ void mma16816(float* c, const uint32_t* a, const uint32_t* b) {
    asm volatile(
        "mma.sync.aligned.m16n8k16.row.col.f32.f16.f16.f32 "
        "{%0,%1,%2,%3}, {%4,%5,%6,%7}, {%8,%9}, {%0,%1,%2,%3};"
        : "+f"(c[0]), "+f"(c[1]), "+f"(c[2]), "+f"(c[3])
        : "r"(a[0]), "r"(a[1]), "r"(a[2]), "r"(a[3]), "r"(b[0]), "r"(b[1]));
}

__device__ __forceinline__ void ldsm4(uint32_t* r, uint32_t addr) {
    asm volatile("ldmatrix.sync.aligned.m8n8.x4.shared.b16 {%0,%1,%2,%3}, [%4];"
        : "=r"(r[0]), "=r"(r[1]), "=r"(r[2]), "=r"(r[3]) : "r"(addr));
}

__device__ __forceinline__ void cp_async16(uint32_t smem_addr, const void* gptr) {
    asm volatile("cp.async.cg.shared.global [%0], [%1], 16;"
                 :: "r"(smem_addr), "l"(gptr));
}
__device__ __forceinline__ void cp_commit() {
    asm volatile("cp.async.commit_group;" ::: "memory");
}
template <int N>
__device__ __forceinline__ void cp_wait() {
    asm volatile("cp.async.wait_group %0;" :: "n"(N) : "memory");
}

__device__ __forceinline__ uint32_t smem_u32(const void* p) {
    uint32_t a;
    asm("{ .reg .u64 t; cvta.to.shared.u64 t, %1; cvt.u32.u64 %0, t; }"
        : "=r"(a) : "l"(p));
    return a;
}

__device__ __forceinline__ uint32_t packh2(float a, float b) {
    __half2 h = __halves2half2(__float2half(a), __float2half(b));
    return *(uint32_t*)&h;
}

// 64B-row swizzle (flash attention tiles)
__device__ __forceinline__ uint32_t swoff(uint32_t r, uint32_t c) {
    return r * 64u + (((c ^ (r >> 1)) & 3u) << 4);
}
// 128B-row swizzle (GEMM BK=64 tiles): chunk c in 0..7
__device__ __forceinline__ uint32_t sw128(uint32_t r, uint32_t c) {
    return r * 128u + (((c ^ (r & 7u)) & 7u) << 4);
}

// ====== NT GEMM 128x128 tile, BK=64: single-product fp16 HMMA, 2 CTAs/SM ===
#define ARRB  16384            // 128 rows * 128 B
#define STGB  (2 * ARRB)       // Ahi|Bhi = 32768 B
#define STAGES 3
#define GSMEM (STAGES * STGB)  // 98304 B
#define FT_STRIDE 132          // padded fp32 tile row stride (floats)

template <bool QKV_EPI>
__global__ void __launch_bounds__(256, 2) gemm_fp16(
    const __half* __restrict__ Ahi, const __half* __restrict__ Bhi,
    float* __restrict__ C, int K, int lda, int ldb, int ldc,
    const int* __restrict__ pos, const float* __restrict__ prior,
    __half* __restrict__ qhi, __half* __restrict__ khi,
    __half* __restrict__ vthi)
{
    extern __shared__ char smem[];
    const uint32_t smem_b = smem_u32(smem);
    const int tid = threadIdx.x;
    const int wid = tid >> 5;
    const int lane = tid & 31;
    const int g  = lane >> 2;
    const int tc = lane & 3;
    const int warp_m = wid & 3;
    const int warp_n = wid >> 2;
    const int KT = K / 64;

    Ahi += (size_t)blockIdx.y * 128 * lda;
    Bhi += (size_t)blockIdx.x * 128 * ldb;

    const int lr0 = tid >> 3;
    const int lc0 = tid & 7;
    const uint32_t stsOff[4] = {
        sw128(lr0,      lc0), sw128(lr0 + 32, lc0),
        sw128(lr0 + 64, lc0), sw128(lr0 + 96, lc0)
    };

    const uint32_t aRow0 = warp_m * 32 + ((lane >> 3) & 1) * 8 + (lane & 7);
    const uint32_t aSel  = (uint32_t)lane >> 4;
    const uint32_t bSel  = ((uint32_t)lane >> 3) & 1;
    const uint32_t bRowB = warp_n * 64 + ((lane >> 4) & 1) * 8 + (lane & 7);

    float acc[2][8][4];
#pragma unroll
    for (int i = 0; i < 2; i++)
#pragma unroll
        for (int j = 0; j < 8; j++)
#pragma unroll
            for (int e = 0; e < 4; e++) acc[i][j][e] = 0.0f;

    auto issue_stage = [&](int kt, int s) {
        const uint32_t sb = smem_b + s * STGB;
        int kk = kt * 64;
#pragma unroll
        for (int t = 0; t < 4; t++) {
            int r = lr0 + t * 32;
            cp_async16(sb + stsOff[t],        Ahi + (size_t)r * lda + kk + lc0 * 8);
            cp_async16(sb + ARRB + stsOff[t], Bhi + (size_t)r * ldb + kk + lc0 * 8);
        }
    };

#pragma unroll
    for (int p = 0; p < STAGES - 1; p++) {
        if (p < KT) issue_stage(p, p);
        cp_commit();
    }

    int s = 0;
    for (int kt = 0; kt < KT; kt++) {
        cp_wait<STAGES - 2>();
        __syncthreads();

        int nk = kt + STAGES - 1;
        int ns = s + STAGES - 1; if (ns >= STAGES) ns -= STAGES;
        if (nk < KT) issue_stage(nk, ns);
        cp_commit();

        const uint32_t sa_hi = smem_b + s * STGB;
        const uint32_t sb_hi = sa_hi + ARRB;

#pragma unroll
        for (int ks = 0; ks < 4; ks++) {
            const uint32_t ac = ks * 2 + aSel;
            uint32_t AH[2][4];
#pragma unroll
            for (int mt = 0; mt < 2; mt++)
                ldsm4(AH[mt], sa_hi + sw128(aRow0 + mt * 16, ac));
            const uint32_t bc = ks * 2 + bSel;
#pragma unroll
            for (int p = 0; p < 4; p++) {
                uint32_t BH[4];
                ldsm4(BH, sb_hi + sw128(bRowB + p * 16, bc));
#pragma unroll
                for (int mt = 0; mt < 2; mt++)
#pragma unroll
                    for (int q = 0; q < 2; q++)
                        mma16816(acc[mt][2 * p + q], AH[mt], BH + 2 * q);
            }
        }
        if (++s == STAGES) s = 0;
    }

    if (!QKV_EPI) {
        const int rowb = blockIdx.y * 128 + warp_m * 32;
        const int colb = blockIdx.x * 128 + warp_n * 64;
#pragma unroll
        for (int mt = 0; mt < 2; mt++)
#pragma unroll
            for (int nt = 0; nt < 8; nt++) {
                int rr = rowb + mt * 16 + g;
                int cc = colb + nt * 8 + tc * 2;
                *(float2*)(C + (size_t)rr * ldc + cc) =
                    make_float2(acc[mt][nt][0], acc[mt][nt][1]);
                *(float2*)(C + (size_t)(rr + 8) * ldc + cc) =
                    make_float2(acc[mt][nt][2], acc[mt][nt][3]);
            }
        return;
    }

    // ================= fused QKV projection epilogue =================
    __syncthreads();
    float* ft     = (float*)smem;                            // 128 x 132 fp32
    float* eta_sm = (float*)(smem + 128 * FT_STRIDE * 4);    // 128 floats

    const int s0 = blockIdx.y * 128;
#pragma unroll
    for (int mt = 0; mt < 2; mt++)
#pragma unroll
        for (int nt = 0; nt < 8; nt++) {
            int rr = warp_m * 32 + mt * 16 + g;
            int cc = warp_n * 64 + nt * 8 + tc * 2;
            *(float2*)(ft + rr * FT_STRIDE + cc) =
                make_float2(acc[mt][nt][0], acc[mt][nt][1]);
            *(float2*)(ft + (rr + 8) * FT_STRIDE + cc) =
                make_float2(acc[mt][nt][2], acc[mt][nt][3]);
        }
    if (tid < 128) {
        float pr = prior[s0 + tid];
        eta_sm[tid] = fminf(fmaxf(1.0f + 0.5f * pr, 0.5f), 2.0f);  // gamma==eta
    }
    __syncthreads();

    const int bx = blockIdx.x;
    if (bx < 40) {
        // RoPE path (q: bx 0..31, k: bx 32..39)
        const int r  = tid >> 1;            // row 0..127
        const int dh = (tid & 1) << 5;      // 0 / 32
        const int ss = s0 + r;
        const float p = (float)pos[ss];
        const float scale = (bx < 32) ? 0.08838834764831845f : eta_sm[r];

        uint32_t w1[16], w2[16];
#pragma unroll
        for (int jv = 0; jv < 8; jv++) {
            float4 X1 = *(const float4*)(ft + r * FT_STRIDE + dh + jv * 4);
            float4 X2 = *(const float4*)(ft + r * FT_STRIDE + dh + 64 + jv * 4);
            float y1[4], y2[4];
            const float* x1 = (const float*)&X1;
            const float* x2 = (const float*)&X2;
#pragma unroll
            for (int e = 0; e < 4; e++) {
                int d = dh + jv * 4 + e;
                float inv = exp2f(-0.2076245760856056f * (float)d);
                float sn, cs;
                sincosf(p * inv, &sn, &cs);
                y1[e] = (x1[e] * cs - x2[e] * sn) * scale;
                y2[e] = (x2[e] * cs + x1[e] * sn) * scale;
            }
            w1[jv * 2]     = packh2(y1[0], y1[1]);
            w1[jv * 2 + 1] = packh2(y1[2], y1[3]);
            w2[jv * 2]     = packh2(y2[0], y2[1]);
            w2[jv * 2 + 1] = packh2(y2[2], y2[3]);
        }
        __half* dst = (bx < 32)
            ? qhi + (size_t)ss * HID + bx * 128
            : khi + (size_t)ss * KVHID + (bx - 32) * 128;
#pragma unroll
        for (int k4 = 0; k4 < 4; k4++) {
            *(uint4*)(dst + dh + k4 * 8) =
                make_uint4(w1[k4 * 4], w1[k4 * 4 + 1], w1[k4 * 4 + 2], w1[k4 * 4 + 3]);
            *(uint4*)(dst + dh + 64 + k4 * 8) =
                make_uint4(w2[k4 * 4], w2[k4 * 4 + 1], w2[k4 * 4 + 2], w2[k4 * 4 + 3]);
        }
    } else {
        // V path: eta scale + transpose -> vThi[(hv*128+cc)*S + s]
        const int hv = bx - 40;
#pragma unroll
        for (int ci = 0; ci < 16; ci++) {
            int cc = wid * 16 + ci;
            size_t base = (size_t)(hv * 128 + cc) * S + s0;
#pragma unroll
            for (int q2 = 0; q2 < 4; q2++) {
                int r = lane + 32 * q2;
                vthi[base + r] = __float2half(ft[r * FT_STRIDE + cc] * eta_sm[r]);
            }
        }
    }
}

// ======================= fused flash attention ==============================
#define FA_QHI   0
#define FA_BIAS  32768
#define FA_U     36864
#define FA_KV0   40960
#define FA_KSTG  65536
#define FA_SMEM  (FA_KV0 + 2 * FA_KSTG)   // 172032

__global__ void __launch_bounds__(256, 1) flash_attn(
    const __half* __restrict__ qhi,
    const __half* __restrict__ khi, const __half* __restrict__ vthi,
    const float* __restrict__ prior, const float* __restrict__ m1,
    const float* __restrict__ m2,
    __half* __restrict__ cxhi)
{
    const int h    = blockIdx.x;
    const int by   = 7 - (int)blockIdx.y;
    const int hk   = h >> 2;
    const int nblk = by + 1;

    extern __shared__ char smem[];
    const uint32_t sb = smem_u32(smem);
    const int tid = threadIdx.x;
    const int wid = tid >> 5;
    const int lane = tid & 31;
    const int g = lane >> 2, tc = lane & 3;

    const float l1 = m1[h], l2 = m2[h];

    float* biasb = (float*)(smem + FA_BIAS);
    float* ub    = (float*)(smem + FA_U);
    for (int j = tid; j < S; j += 256) {
        float pj = prior[j];
        biasb[j] = fminf(fmaxf(pj, -5.0f), 5.0f) * l1;
        ub[j]    = 1.0f + 0.5f * pj * l2;
    }

    {
        const __half* qh = qhi + (size_t)(by * 128) * HID + h * D;
#pragma unroll
        for (int t = 0; t < 8; t++) {
            int id = tid + t * 256;
            int r = id >> 4, cc = id & 15;
            uint32_t dst = (uint32_t)(cc >> 2) * 8192 + swoff(r, cc & 3);
            cp_async16(sb + FA_QHI + dst, qh + (size_t)r * HID + cc * 8);
        }
    }

    auto issue_kv = [&](int j, int st) {
        const uint32_t kb = sb + FA_KV0 + st * FA_KSTG;
        const __half* kp = khi  + (size_t)(j * 128) * KVHID + hk * D;
        const __half* vp = vthi + (size_t)(hk * 128) * S + j * 128;
#pragma unroll
        for (int t = 0; t < 8; t++) {
            int id = tid + t * 256;
            int r = id >> 4, cc = id & 15;
            uint32_t dst = (uint32_t)(cc >> 2) * 8192 + swoff(r, cc & 3);
            cp_async16(kb + dst,         kp + (size_t)r * KVHID + cc * 8);
            cp_async16(kb + 32768 + dst, vp + (size_t)r * S + cc * 8);
        }
    };

    issue_kv(0, 0);
    cp_commit();

    const uint32_t aRowQ = wid * 16 + ((lane >> 3) & 1) * 8 + (lane & 7);
    const uint32_t aSel  = (uint32_t)lane >> 4;
    const uint32_t bSel  = ((uint32_t)lane >> 3) & 1;
    const uint32_t bRow  = ((lane >> 4) & 1) * 8 + (lane & 7);

    float oacc[16][4];
#pragma unroll
    for (int i = 0; i < 16; i++)
#pragma unroll
        for (int e = 0; e < 4; e++) oacc[i][e] = 0.0f;
    float mrun0 = -1e30f, mrun1 = -1e30f;
    float srun0 = 0.0f,   srun1 = 0.0f;

    const int row0 = wid * 16 + g;

    for (int j = 0; j < nblk; j++) {
        const int st = j & 1;
        if (j + 1 < nblk) { issue_kv(j + 1, st ^ 1); cp_commit(); cp_wait<1>(); }
        else              { cp_wait<0>(); }
        __syncthreads();

        const uint32_t kb = sb + FA_KV0 + st * FA_KSTG;
        const uint32_t vb = kb + 32768;

        float sacc[16][4];
#pragma unroll
        for (int i = 0; i < 16; i++)
#pragma unroll
            for (int e = 0; e < 4; e++) sacc[i][e] = 0.0f;

#pragma unroll
        for (int kf = 0; kf < 8; kf++) {
            uint32_t sub = (uint32_t)(kf >> 1) * 8192;
            uint32_t kc  = (uint32_t)(kf & 1) * 2;
            uint32_t AH[4];
            ldsm4(AH, sb + FA_QHI + sub + swoff(aRowQ, kc + aSel));
#pragma unroll
            for (int p = 0; p < 8; p++) {
                uint32_t BH[4];
                ldsm4(BH, kb + sub + swoff(bRow + p * 16, kc + bSel));
#pragma unroll
                for (int q = 0; q < 2; q++)
                    mma16816(sacc[2 * p + q], AH, BH + 2 * q);
            }
        }

        const float* bias = biasb + j * 128;
        const float* uu   = ub + j * 128;
        const bool diag = (j == by);

        float mb0 = -1e30f, mb1 = -1e30f;
#pragma unroll
        for (int nt = 0; nt < 16; nt++) {
            int k0 = nt * 8 + tc * 2;
            float b0 = bias[k0], b1 = bias[k0 + 1];
            float a0 = sacc[nt][0] + b0;
            float a1 = sacc[nt][1] + b1;
            float a2 = sacc[nt][2] + b0;
            float a3 = sacc[nt][3] + b1;
            if (diag) {
                if (k0     > row0)     a0 = -1e30f;
                if (k0 + 1 > row0)     a1 = -1e30f;
                if (k0     > row0 + 8) a2 = -1e30f;
                if (k0 + 1 > row0 + 8) a3 = -1e30f;
            }
            sacc[nt][0] = a0; sacc[nt][1] = a1;
            sacc[nt][2] = a2; sacc[nt][3] = a3;
            mb0 = fmaxf(mb0, fmaxf(a0, a1));
            mb1 = fmaxf(mb1, fmaxf(a2, a3));
        }
        mb0 = fmaxf(mb0, __shfl_xor_sync(0xffffffffu, mb0, 1));
        mb0 = fmaxf(mb0, __shfl_xor_sync(0xffffffffu, mb0, 2));
        mb1 = fmaxf(mb1, __shfl_xor_sync(0xffffffffu, mb1, 1));
        mb1 = fmaxf(mb1, __shfl_xor_sync(0xffffffffu, mb1, 2));

        float mn0 = fmaxf(mrun0, mb0);
        float mn1 = fmaxf(mrun1, mb1);
        float sc0 = __expf(mrun0 - mn0);
        float sc1 = __expf(mrun1 - mn1);
        mrun0 = mn0; mrun1 = mn1;

        float rs0 = 0.0f, rs1 = 0.0f;
#pragma unroll
        for (int nt = 0; nt < 16; nt++) {
            int k0 = nt * 8 + tc * 2;
            float u0 = uu[k0], u1 = uu[k0 + 1];
            float e0 = __expf(sacc[nt][0] - mn0) * u0;
            float e1 = __expf(sacc[nt][1] - mn0) * u1;
            float e2 = __expf(sacc[nt][2] - mn1) * u0;
            float e3 = __expf(sacc[nt][3] - mn1) * u1;
            sacc[nt][0] = e0; sacc[nt][1] = e1;
            sacc[nt][2] = e2; sacc[nt][3] = e3;
            rs0 += e0 + e1; rs1 += e2 + e3;
            oacc[nt][0] *= sc0; oacc[nt][1] *= sc0;
            oacc[nt][2] *= sc1; oacc[nt][3] *= sc1;
        }
        rs0 += __shfl_xor_sync(0xffffffffu, rs0, 1);
        rs0 += __shfl_xor_sync(0xffffffffu, rs0, 2);
        rs1 += __shfl_xor_sync(0xffffffffu, rs1, 1);
        rs1 += __shfl_xor_sync(0xffffffffu, rs1, 2);
        srun0 = srun0 * sc0 + rs0;
        srun1 = srun1 * sc1 + rs1;

#pragma unroll
        for (int kf = 0; kf < 8; kf++) {
            uint32_t AP[4];
            AP[0] = packh2(sacc[2 * kf][0],     sacc[2 * kf][1]);
            AP[1] = packh2(sacc[2 * kf][2],     sacc[2 * kf][3]);
            AP[2] = packh2(sacc[2 * kf + 1][0], sacc[2 * kf + 1][1]);
            AP[3] = packh2(sacc[2 * kf + 1][2], sacc[2 * kf + 1][3]);
            uint32_t sub = (uint32_t)(kf >> 1) * 8192;
            uint32_t kc  = (uint32_t)(kf & 1) * 2;
#pragma unroll
            for (int p = 0; p < 8; p++) {
                uint32_t BV[4];
                ldsm4(BV, vb + sub + swoff(bRow + p * 16, kc + bSel));
                mma16816(oacc[2 * p],     AP, BV);
                mma16816(oacc[2 * p + 1], AP, BV + 2);
            }
        }
        __syncthreads();
    }

    float inv0 = 1.0f / srun0;
    float inv1 = 1.0f / srun1;
    int grow = by * 128 + wid * 16 + g;
    __half* Hp = cxhi + (size_t)grow * HID + h * D + tc * 2;
#pragma unroll
    for (int nt = 0; nt < 16; nt++) {
        *(__half2*)(Hp + nt * 8) =
            __halves2half2(__float2half(oacc[nt][0] * inv0),
                           __float2half(oacc[nt][1] * inv0));
        *(__half2*)(Hp + (size_t)8 * HID + nt * 8) =
            __halves2half2(__float2half(oacc[nt][2] * inv1),
                           __float2half(oacc[nt][3] * inv1));
    }
}

// ---------------- generic fp32 -> fp16 convert ------------------------------
__global__ void cvt_kernel(const float4* __restrict__ src,
                           uint2* __restrict__ dst, int n4)
{
    int stride = gridDim.x * blockDim.x;
    for (int i = blockIdx.x * blockDim.x + threadIdx.x; i < n4; i += stride) {
        float4 v = src[i];
        __half2 a = __floats2half2_rn(v.x, v.y);
        __half2 b = __floats2half2_rn(v.z, v.w);
        uint2 w;
        w.x = *(uint32_t*)&a;
        w.y = *(uint32_t*)&b;
        dst[i] = w;
    }
}

// ---------------- launch ----------------------------------------------------
extern "C" void kernel_launch(void* const* d_in, const int* in_sizes, int n_in,
                              void* d_out, int out_size)
{
    const float* hs    = (const float*)d_in[0];
    const int*   pos   = (const int*)  d_in[2];
    const float* Wq    = (const float*)d_in[3];
    const float* Wk    = (const float*)d_in[4];
    const float* Wv    = (const float*)d_in[5];
    const float* Wo    = (const float*)d_in[6];
    const float* prior = (const float*)d_in[7];
    const float* m1    = (const float*)d_in[8];
    const float* m2    = (const float*)d_in[9];
    float* out = (float*)d_out;

    __half *hshi, *wqkvhi, *wohi, *qhi, *khi, *vthi, *cxhi;
    cudaGetSymbolAddress((void**)&hshi,  g_hs_hi);
    cudaGetSymbolAddress((void**)&wqkvhi,g_wqkv_hi);
    cudaGetSymbolAddress((void**)&wohi,  g_wo_hi);
    cudaGetSymbolAddress((void**)&qhi,   g_q_hi);
    cudaGetSymbolAddress((void**)&khi,   g_k_hi);
    cudaGetSymbolAddress((void**)&vthi,  g_vT_hi);
    cudaGetSymbolAddress((void**)&cxhi,  g_ctx_hi);

    static cudaStream_t s1 = nullptr;
    static cudaEvent_t evF = nullptr, evO = nullptr;
    static int configured = 0;
    if (!configured) {
        cudaFuncSetAttribute(gemm_fp16<true>,
            cudaFuncAttributeMaxDynamicSharedMemorySize, GSMEM);
        cudaFuncSetAttribute(gemm_fp16<false>,
            cudaFuncAttributeMaxDynamicSharedMemorySize, GSMEM);
        cudaFuncSetAttribute(flash_attn,
            cudaFuncAttributeMaxDynamicSharedMemorySize, FA_SMEM);
        cudaStreamCreateWithFlags(&s1, cudaStreamNonBlocking);
        cudaEventCreateWithFlags(&evF, cudaEventDisableTiming);
        cudaEventCreateWithFlags(&evO, cudaEventDisableTiming);
        configured = 1;
    }

    dim3 blk(256);

    // 0a) stream0: hs convert, then FORK s1 off the capture stream (legal
    //     capture pattern: side stream must join via an event recorded on
    //     the origin stream).
    cvt_kernel<<<1024, 256>>>((const float4*)hs, (uint2*)hshi, S * HID / 4);
    cudaEventRecord(evF, 0);
    cudaStreamWaitEvent(s1, evF, 0);

    // 0b) stream1: Wo convert — overlaps remaining cvts + QKV GEMM + flash
    cvt_kernel<<<256, 256, 0, s1>>>((const float4*)Wo, (uint2*)wohi,
                                    HID * HID / 4);
    cudaEventRecord(evO, s1);

    // 0c) stream0: converts needed by the QKV GEMM
    cvt_kernel<<<1024, 256>>>((const float4*)Wq, (uint2*)wqkvhi, HID * HID / 4);
    cvt_kernel<<<1024, 256>>>((const float4*)Wk,
        (uint2*)(wqkvhi + (size_t)HID * HID), KVHID * HID / 4);
    cvt_kernel<<<1024, 256>>>((const float4*)Wv,
        (uint2*)(wqkvhi + (size_t)(HID + KVHID) * HID), KVHID * HID / 4);

    // 1) merged projection GEMM (full 48x8 grid) with fused epilogue
    gemm_fp16<true><<<dim3(QKVW / 128, S / 128), blk, GSMEM>>>(
        hshi, wqkvhi, nullptr, HID, HID, HID, 0,
        pos, prior, qhi, khi, vthi);

    // 2) fused flash attention -> ctx fp16 (Wo cvt finishing on s1)
    flash_attn<<<dim3(H, S / 128), blk, FA_SMEM>>>(
        qhi, khi, vthi, prior, m1, m2, cxhi);

    // 3) out = ctx @ Wo^T, gated on Wo conversion (join s1 back into capture)
    cudaStreamWaitEvent(0, evO, 0);
    gemm_fp16<false><<<dim3(HID / 128, S / 128), blk, GSMEM>>>(
        cxhi, wohi, out, HID, HID, HID, HID,
        nullptr, nullptr, nullptr, nullptr, nullptr);
}

// round 17
// speedup vs baseline: 1.1306x; 1.0113x over previous
#include <cuda_runtime.h>
#include <cuda_fp16.h>
#include <math.h>
#include <stdint.h>

// Problem constants (B=1)
#define S     1024
#define H     32
#define HKV   8
#define D     128
#define HID   4096
#define KVHID 1024
#define QKVW  (HID + 2 * KVHID)   // 6144
#define GROUPS 4

// ---------------- scratch (static device globals: no allocs allowed) -------
__device__ __half g_hs_hi[(size_t)S * HID];
__device__ __half g_wqkv_hi[(size_t)QKVW * HID];
__device__ __half g_wo_hi[(size_t)HID * HID];
__device__ __half g_q_hi[(size_t)S * HID];
__device__ __half g_k_hi[(size_t)S * KVHID];
__device__ __half g_vT_hi[(size_t)KVHID * S];
__device__ __half g_ctx_hi[(size_t)S * HID];

// ---------------- helpers ---------------------------------------------------
__device__ __forceinline__ void mma16816(float* c, const uint32_t* a, const uint32_t* b) {
    asm volatile(
        "mma.sync.aligned.m16n8k16.row.col.f32.f16.f16.f32 "
        "{%0,%1,%2,%3}, {%4,%5,%6,%7}, {%8,%9}, {%0,%1,%2,%3};"
        : "+f"(c[0]), "+f"(c[1]), "+f"(c[2]), "+f"(c[3])
        : "r"(a[0]), "r"(a[1]), "r"(a[2]), "r"(a[3]), "r"(b[0]), "r"(b[1]));
}

__device__ __forceinline__ void ldsm4(uint32_t* r, uint32_t addr) {
    asm volatile("ldmatrix.sync.aligned.m8n8.x4.shared.b16 {%0,%1,%2,%3}, [%4];"
        : "=r"(r[0]), "=r"(r[1]), "=r"(r[2]), "=r"(r[3]) : "r"(addr));
}

__device__ __forceinline__ void cp_async16(uint32_t smem_addr, const void* gptr) {
    asm volatile("cp.async.cg.shared.global [%0], [%1], 16;"
                 :: "r"(smem_addr), "l"(gptr));
}
__device__ __forceinline__ void cp_commit() {
    asm volatile("cp.async.commit_group;" ::: "memory");
}
template <int N>
__device__ __forceinline__ void cp_wait() {
    asm volatile("cp.async.wait_group %0;" :: "n"(N) : "memory");
}

__device__ __forceinline__ uint32_t smem_u32(const void* p) {
    uint32_t a;
    asm("{ .reg .u64 t; cvta.to.shared.u64 t, %1; cvt.u32.u64 %0, t; }"
        : "=r"(a) : "l"(p));
    return a;
}

__device__ __forceinline__ uint32_t packh2(float a, float b) {
    __half2 h = __halves2half2(__float2half(a), __float2half(b));
    return *(uint32_t*)&h;
}

// 64B-row swizzle (flash attention tiles)
__device__ __forceinline__ uint32_t swoff(uint32_t r, uint32_t c) {
    return r * 64u + (((c ^ (r >> 1)) & 3u) << 4);
}
// 128B-row swizzle (GEMM BK=64 tiles): chunk c in 0..7
__device__ __forceinline__ uint32_t sw128(uint32_t r, uint32_t c) {
    return r * 128u + (((c ^ (r & 7u)) & 7u) << 4);
}

// ====== NT GEMM 128x128 tile, BK=64: single-product fp16 HMMA, 2 CTAs/SM ===
#define ARRB  16384            // 128 rows * 128 B
#define STGB  (2 * ARRB)       // Ahi|Bhi = 32768 B
#define STAGES 3
#define GSMEM (STAGES * STGB)  // 98304 B
#define FT_STRIDE 132          // padded fp32 tile row stride (floats)

template <bool QKV_EPI>
__global__ void __launch_bounds__(256, 2) gemm_fp16(
    const __half* __restrict__ Ahi, const __half* __restrict__ Bhi,
    float* __restrict__ C, int K, int lda, int ldb, int ldc,
    const int* __restrict__ pos, const float* __restrict__ prior,
    __half* __restrict__ qhi, __half* __restrict__ khi,
    __half* __restrict__ vthi)
{
    extern __shared__ char smem[];
    const uint32_t smem_b = smem_u32(smem);
    const int tid = threadIdx.x;
    const int wid = tid >> 5;
    const int lane = tid & 31;
    const int g  = lane >> 2;
    const int tc = lane & 3;
    const int warp_m = wid & 3;
    const int warp_n = wid >> 2;
    const int KT = K / 64;

    Ahi += (size_t)blockIdx.y * 128 * lda;
    Bhi += (size_t)blockIdx.x * 128 * ldb;

    const int lr0 = tid >> 3;
    const int lc0 = tid & 7;
    const uint32_t stsOff[4] = {
        sw128(lr0,      lc0), sw128(lr0 + 32, lc0),
        sw128(lr0 + 64, lc0), sw128(lr0 + 96, lc0)
    };

    const uint32_t aRow0 = warp_m * 32 + ((lane >> 3) & 1) * 8 + (lane & 7);
    const uint32_t aSel  = (uint32_t)lane >> 4;
    const uint32_t bSel  = ((uint32_t)lane >> 3) & 1;
    const uint32_t bRowB = warp_n * 64 + ((lane >> 4) & 1) * 8 + (lane & 7);

    float acc[2][8][4];
#pragma unroll
    for (int i = 0; i < 2; i++)
#pragma unroll
        for (int j = 0; j < 8; j++)
#pragma unroll
            for (int e = 0; e < 4; e++) acc[i][j][e] = 0.0f;

    auto issue_stage = [&](int kt, int s) {
        const uint32_t sb = smem_b + s * STGB;
        int kk = kt * 64;
#pragma unroll
        for (int t = 0; t < 4; t++) {
            int r = lr0 + t * 32;
            cp_async16(sb + stsOff[t],        Ahi + (size_t)r * lda + kk + lc0 * 8);
            cp_async16(sb + ARRB + stsOff[t], Bhi + (size_t)r * ldb + kk + lc0 * 8);
        }
    };

#pragma unroll
    for (int p = 0; p < STAGES - 1; p++) {
        if (p < KT) issue_stage(p, p);
        cp_commit();
    }

    int s = 0;
    for (int kt = 0; kt < KT; kt++) {
        cp_wait<STAGES - 2>();
        __syncthreads();

        int nk = kt + STAGES - 1;
        int ns = s + STAGES - 1; if (ns >= STAGES) ns -= STAGES;
        if (nk < KT) issue_stage(nk, ns);
        cp_commit();

        const uint32_t sa_hi = smem_b + s * STGB;
        const uint32_t sb_hi = sa_hi + ARRB;

#pragma unroll
        for (int ks = 0; ks < 4; ks++) {
            const uint32_t ac = ks * 2 + aSel;
            uint32_t AH[2][4];
#pragma unroll
            for (int mt = 0; mt < 2; mt++)
                ldsm4(AH[mt], sa_hi + sw128(aRow0 + mt * 16, ac));
            const uint32_t bc = ks * 2 + bSel;
#pragma unroll
            for (int p = 0; p < 4; p++) {
                uint32_t BH[4];
                ldsm4(BH, sb_hi + sw128(bRowB + p * 16, bc));
#pragma unroll
                for (int mt = 0; mt < 2; mt++)
#pragma unroll
                    for (int q = 0; q < 2; q++)
                        mma16816(acc[mt][2 * p + q], AH[mt], BH + 2 * q);
            }
        }
        if (++s == STAGES) s = 0;
    }

    if (!QKV_EPI) {
        const int rowb = blockIdx.y * 128 + warp_m * 32;
        const int colb = blockIdx.x * 128 + warp_n * 64;
#pragma unroll
        for (int mt = 0; mt < 2; mt++)
#pragma unroll
            for (int nt = 0; nt < 8; nt++) {
                int rr = rowb + mt * 16 + g;
                int cc = colb + nt * 8 + tc * 2;
                *(float2*)(C + (size_t)rr * ldc + cc) =
                    make_float2(acc[mt][nt][0], acc[mt][nt][1]);
                *(float2*)(C + (size_t)(rr + 8) * ldc + cc) =
                    make_float2(acc[mt][nt][2], acc[mt][nt][3]);
            }
        return;
    }

    // ================= fused QKV projection epilogue =================
    __syncthreads();
    float* ft     = (float*)smem;                            // 128 x 132 fp32
    float* eta_sm = (float*)(smem + 128 * FT_STRIDE * 4);    // 128 floats

    const int s0 = blockIdx.y * 128;
#pragma unroll
    for (int mt = 0; mt < 2; mt++)
#pragma unroll
        for (int nt = 0; nt < 8; nt++) {
            int rr = warp_m * 32 + mt * 16 + g;
            int cc = warp_n * 64 + nt * 8 + tc * 2;
            *(float2*)(ft + rr * FT_STRIDE + cc) =
                make_float2(acc[mt][nt][0], acc[mt][nt][1]);
            *(float2*)(ft + (rr + 8) * FT_STRIDE + cc) =
                make_float2(acc[mt][nt][2], acc[mt][nt][3]);
        }
    if (tid < 128) {
        float pr = prior[s0 + tid];
        eta_sm[tid] = fminf(fmaxf(1.0f + 0.5f * pr, 0.5f), 2.0f);  // gamma==eta
    }
    __syncthreads();

    const int bx = blockIdx.x;
    if (bx < 40) {
        // RoPE path (q: bx 0..31, k: bx 32..39)
        const int r  = tid >> 1;            // row 0..127
        const int dh = (tid & 1) << 5;      // 0 / 32
        const int ss = s0 + r;
        const float p = (float)pos[ss];
        const float scale = (bx < 32) ? 0.08838834764831845f : eta_sm[r];

        uint32_t w1[16], w2[16];
#pragma unroll
        for (int jv = 0; jv < 8; jv++) {
            float4 X1 = *(const float4*)(ft + r * FT_STRIDE + dh + jv * 4);
            float4 X2 = *(const float4*)(ft + r * FT_STRIDE + dh + 64 + jv * 4);
            float y1[4], y2[4];
            const float* x1 = (const float*)&X1;
            const float* x2 = (const float*)&X2;
#pragma unroll
            for (int e = 0; e < 4; e++) {
                int d = dh + jv * 4 + e;
                float inv = exp2f(-0.2076245760856056f * (float)d);
                float sn, cs;
                sincosf(p * inv, &sn, &cs);
                y1[e] = (x1[e] * cs - x2[e] * sn) * scale;
                y2[e] = (x2[e] * cs + x1[e] * sn) * scale;
            }
            w1[jv * 2]     = packh2(y1[0], y1[1]);
            w1[jv * 2 + 1] = packh2(y1[2], y1[3]);
            w2[jv * 2]     = packh2(y2[0], y2[1]);
            w2[jv * 2 + 1] = packh2(y2[2], y2[3]);
        }
        __half* dst = (bx < 32)
            ? qhi + (size_t)ss * HID + bx * 128
            : khi + (size_t)ss * KVHID + (bx - 32) * 128;
#pragma unroll
        for (int k4 = 0; k4 < 4; k4++) {
            *(uint4*)(dst + dh + k4 * 8) =
                make_uint4(w1[k4 * 4], w1[k4 * 4 + 1], w1[k4 * 4 + 2], w1[k4 * 4 + 3]);
            *(uint4*)(dst + dh + 64 + k4 * 8) =
                make_uint4(w2[k4 * 4], w2[k4 * 4 + 1], w2[k4 * 4 + 2], w2[k4 * 4 + 3]);
        }
    } else {
        // V path: eta scale + transpose -> vThi[(hv*128+cc)*S + s]
        const int hv = bx - 40;
#pragma unroll
        for (int ci = 0; ci < 16; ci++) {
            int cc = wid * 16 + ci;
            size_t base = (size_t)(hv * 128 + cc) * S + s0;
#pragma unroll
            for (int q2 = 0; q2 < 4; q2++) {
                int r = lane + 32 * q2;
                vthi[base + r] = __float2half(ft[r * FT_STRIDE + cc] * eta_sm[r]);
            }
        }
    }
}

// ======================= fused flash attention ==============================
#define FA_QHI   0
#define FA_BIAS  32768
#define FA_U     36864
#define FA_KV0   40960
#define FA_KSTG  65536
#define FA_SMEM  (FA_KV0 + 2 * FA_KSTG)   // 172032

__global__ void __launch_bounds__(256, 1) flash_attn(
    const __half* __restrict__ qhi,
    const __half* __restrict__ khi, const __half* __restrict__ vthi,
    const float* __restrict__ prior, const float* __restrict__ m1,
    const float* __restrict__ m2,
    __half* __restrict__ cxhi)
{
    const int h    = blockIdx.x;
    const int by   = 7 - (int)blockIdx.y;
    const int hk   = h >> 2;
    const int nblk = by + 1;

    extern __shared__ char smem[];
    const uint32_t sb = smem_u32(smem);
    const int tid = threadIdx.x;
    const int wid = tid >> 5;
    const int lane = tid & 31;
    const int g = lane >> 2, tc = lane & 3;

    const float l1 = m1[h], l2 = m2[h];

    float* biasb = (float*)(smem + FA_BIAS);
    float* ub    = (float*)(smem + FA_U);
    for (int j = tid; j < S; j += 256) {
        float pj = prior[j];
        biasb[j] = fminf(fmaxf(pj, -5.0f), 5.0f) * l1;
        ub[j]    = 1.0f + 0.5f * pj * l2;
    }

    {
        const __half* qh = qhi + (size_t)(by * 128) * HID + h * D;
#pragma unroll
        for (int t = 0; t < 8; t++) {
            int id = tid + t * 256;
            int r = id >> 4, cc = id & 15;
            uint32_t dst = (uint32_t)(cc >> 2) * 8192 + swoff(r, cc & 3);
            cp_async16(sb + FA_QHI + dst, qh + (size_t)r * HID + cc * 8);
        }
    }

    auto issue_kv = [&](int j, int st) {
        const uint32_t kb = sb + FA_KV0 + st * FA_KSTG;
        const __half* kp = khi  + (size_t)(j * 128) * KVHID + hk * D;
        const __half* vp = vthi + (size_t)(hk * 128) * S + j * 128;
#pragma unroll
        for (int t = 0; t < 8; t++) {
            int id = tid + t * 256;
            int r = id >> 4, cc = id & 15;
            uint32_t dst = (uint32_t)(cc >> 2) * 8192 + swoff(r, cc & 3);
            cp_async16(kb + dst,         kp + (size_t)r * KVHID + cc * 8);
            cp_async16(kb + 32768 + dst, vp + (size_t)r * S + cc * 8);
        }
    };

    issue_kv(0, 0);
    cp_commit();

    const uint32_t aRowQ = wid * 16 + ((lane >> 3) & 1) * 8 + (lane & 7);
    const uint32_t aSel  = (uint32_t)lane >> 4;
    const uint32_t bSel  = ((uint32_t)lane >> 3) & 1;
    const uint32_t bRow  = ((lane >> 4) & 1) * 8 + (lane & 7);

    float oacc[16][4];
#pragma unroll
    for (int i = 0; i < 16; i++)
#pragma unroll
        for (int e = 0; e < 4; e++) oacc[i][e] = 0.0f;
    float mrun0 = -1e30f, mrun1 = -1e30f;
    float srun0 = 0.0f,   srun1 = 0.0f;

    const int row0 = wid * 16 + g;

    for (int j = 0; j < nblk; j++) {
        const int st = j & 1;
        if (j + 1 < nblk) { issue_kv(j + 1, st ^ 1); cp_commit(); cp_wait<1>(); }
        else              { cp_wait<0>(); }
        __syncthreads();

        const uint32_t kb = sb + FA_KV0 + st * FA_KSTG;
        const uint32_t vb = kb + 32768;

        float sacc[16][4];
#pragma unroll
        for (int i = 0; i < 16; i++)
#pragma unroll
            for (int e = 0; e < 4; e++) sacc[i][e] = 0.0f;

#pragma unroll
        for (int kf = 0; kf < 8; kf++) {
            uint32_t sub = (uint32_t)(kf >> 1) * 8192;
            uint32_t kc  = (uint32_t)(kf & 1) * 2;
            uint32_t AH[4];
            ldsm4(AH, sb + FA_QHI + sub + swoff(aRowQ, kc + aSel));
#pragma unroll
            for (int p = 0; p < 8; p++) {
                uint32_t BH[4];
                ldsm4(BH, kb + sub + swoff(bRow + p * 16, kc + bSel));
#pragma unroll
                for (int q = 0; q < 2; q++)
                    mma16816(sacc[2 * p + q], AH, BH + 2 * q);
            }
        }

        const float* bias = biasb + j * 128;
        const float* uu   = ub + j * 128;
        const bool diag = (j == by);

        float mb0 = -1e30f, mb1 = -1e30f;
#pragma unroll
        for (int nt = 0; nt < 16; nt++) {
            int k0 = nt * 8 + tc * 2;
            float b0 = bias[k0], b1 = bias[k0 + 1];
            float a0 = sacc[nt][0] + b0;
            float a1 = sacc[nt][1] + b1;
            float a2 = sacc[nt][2] + b0;
            float a3 = sacc[nt][3] + b1;
            if (diag) {
                if (k0     > row0)     a0 = -1e30f;
                if (k0 + 1 > row0)     a1 = -1e30f;
                if (k0     > row0 + 8) a2 = -1e30f;
                if (k0 + 1 > row0 + 8) a3 = -1e30f;
            }
            sacc[nt][0] = a0; sacc[nt][1] = a1;
            sacc[nt][2] = a2; sacc[nt][3] = a3;
            mb0 = fmaxf(mb0, fmaxf(a0, a1));
            mb1 = fmaxf(mb1, fmaxf(a2, a3));
        }
        mb0 = fmaxf(mb0, __shfl_xor_sync(0xffffffffu, mb0, 1));
        mb0 = fmaxf(mb0, __shfl_xor_sync(0xffffffffu, mb0, 2));
        mb1 = fmaxf(mb1, __shfl_xor_sync(0xffffffffu, mb1, 1));
        mb1 = fmaxf(mb1, __shfl_xor_sync(0xffffffffu, mb1, 2));

        float mn0 = fmaxf(mrun0, mb0);
        float mn1 = fmaxf(mrun1, mb1);
        float sc0 = __expf(mrun0 - mn0);
        float sc1 = __expf(mrun1 - mn1);
        mrun0 = mn0; mrun1 = mn1;

        float rs0 = 0.0f, rs1 = 0.0f;
#pragma unroll
        for (int nt = 0; nt < 16; nt++) {
            int k0 = nt * 8 + tc * 2;
            float u0 = uu[k0], u1 = uu[k0 + 1];
            float e0 = __expf(sacc[nt][0] - mn0) * u0;
            float e1 = __expf(sacc[nt][1] - mn0) * u1;
            float e2 = __expf(sacc[nt][2] - mn1) * u0;
            float e3 = __expf(sacc[nt][3] - mn1) * u1;
            sacc[nt][0] = e0; sacc[nt][1] = e1;
            sacc[nt][2] = e2; sacc[nt][3] = e3;
            rs0 += e0 + e1; rs1 += e2 + e3;
            oacc[nt][0] *= sc0; oacc[nt][1] *= sc0;
            oacc[nt][2] *= sc1; oacc[nt][3] *= sc1;
        }
        rs0 += __shfl_xor_sync(0xffffffffu, rs0, 1);
        rs0 += __shfl_xor_sync(0xffffffffu, rs0, 2);
        rs1 += __shfl_xor_sync(0xffffffffu, rs1, 1);
        rs1 += __shfl_xor_sync(0xffffffffu, rs1, 2);
        srun0 = srun0 * sc0 + rs0;
        srun1 = srun1 * sc1 + rs1;

#pragma unroll
        for (int kf = 0; kf < 8; kf++) {
            uint32_t AP[4];
            AP[0] = packh2(sacc[2 * kf][0],     sacc[2 * kf][1]);
            AP[1] = packh2(sacc[2 * kf][2],     sacc[2 * kf][3]);
            AP[2] = packh2(sacc[2 * kf + 1][0], sacc[2 * kf + 1][1]);
            AP[3] = packh2(sacc[2 * kf + 1][2], sacc[2 * kf + 1][3]);
            uint32_t sub = (uint32_t)(kf >> 1) * 8192;
            uint32_t kc  = (uint32_t)(kf & 1) * 2;
#pragma unroll
            for (int p = 0; p < 8; p++) {
                uint32_t BV[4];
                ldsm4(BV, vb + sub + swoff(bRow + p * 16, kc + bSel));
                mma16816(oacc[2 * p],     AP, BV);
                mma16816(oacc[2 * p + 1], AP, BV + 2);
            }
        }
        __syncthreads();
    }

    float inv0 = 1.0f / srun0;
    float inv1 = 1.0f / srun1;
    int grow = by * 128 + wid * 16 + g;
    __half* Hp = cxhi + (size_t)grow * HID + h * D + tc * 2;
#pragma unroll
    for (int nt = 0; nt < 16; nt++) {
        *(__half2*)(Hp + nt * 8) =
            __halves2half2(__float2half(oacc[nt][0] * inv0),
                           __float2half(oacc[nt][1] * inv0));
        *(__half2*)(Hp + (size_t)8 * HID + nt * 8) =
            __halves2half2(__float2half(oacc[nt][2] * inv1),
                           __float2half(oacc[nt][3] * inv1));
    }
}

// ---------------- fp32 -> fp16 convert (4-way MLP, coalesced) --------------
__global__ void cvt_kernel(const float4* __restrict__ src,
                           uint2* __restrict__ dst, int n4)
{
    const int stride = gridDim.x * blockDim.x;
    int i = blockIdx.x * blockDim.x + threadIdx.x;
    for (; i + 3 * stride < n4; i += 4 * stride) {
        float4 v0 = src[i];
        float4 v1 = src[i + stride];
        float4 v2 = src[i + 2 * stride];
        float4 v3 = src[i + 3 * stride];
        uint2 w0, w1, w2, w3;
        {
            __half2 a = __floats2half2_rn(v0.x, v0.y);
            __half2 b = __floats2half2_rn(v0.z, v0.w);
            w0.x = *(uint32_t*)&a; w0.y = *(uint32_t*)&b;
        }
        {
            __half2 a = __floats2half2_rn(v1.x, v1.y);
            __half2 b = __floats2half2_rn(v1.z, v1.w);
            w1.x = *(uint32_t*)&a; w1.y = *(uint32_t*)&b;
        }
        {
            __half2 a = __floats2half2_rn(v2.x, v2.y);
            __half2 b = __floats2half2_rn(v2.z, v2.w);
            w2.x = *(uint32_t*)&a; w2.y = *(uint32_t*)&b;
        }
        {
            __half2 a = __floats2half2_rn(v3.x, v3.y);
            __half2 b = __floats2half2_rn(v3.z, v3.w);
            w3.x = *(uint32_t*)&a; w3.y = *(uint32_t*)&b;
        }
        dst[i]              = w0;
        dst[i + stride]     = w1;
        dst[i + 2 * stride] = w2;
        dst[i + 3 * stride] = w3;
    }
    for (; i < n4; i += stride) {
        float4 v = src[i];
        __half2 a = __floats2half2_rn(v.x, v.y);
        __half2 b = __floats2half2_rn(v.z, v.w);
        uint2 w;
        w.x = *(uint32_t*)&a;
        w.y = *(uint32_t*)&b;
        dst[i] = w;
    }
}

// ---------------- launch ----------------------------------------------------
extern "C" void kernel_launch(void* const* d_in, const int* in_sizes, int n_in,
                              void* d_out, int out_size)
{
    const float* hs    = (const float*)d_in[0];
    const int*   pos   = (const int*)  d_in[2];
    const float* Wq    = (const float*)d_in[3];
    const float* Wk    = (const float*)d_in[4];
    const float* Wv    = (const float*)d_in[5];
    const float* Wo    = (const float*)d_in[6];
    const float* prior = (const float*)d_in[7];
    const float* m1    = (const float*)d_in[8];
    const float* m2    = (const float*)d_in[9];
    float* out = (float*)d_out;

    __half *hshi, *wqkvhi, *wohi, *qhi, *khi, *vthi, *cxhi;
    cudaGetSymbolAddress((void**)&hshi,  g_hs_hi);
    cudaGetSymbolAddress((void**)&wqkvhi,g_wqkv_hi);
    cudaGetSymbolAddress((void**)&wohi,  g_wo_hi);
    cudaGetSymbolAddress((void**)&qhi,   g_q_hi);
    cudaGetSymbolAddress((void**)&khi,   g_k_hi);
    cudaGetSymbolAddress((void**)&vthi,  g_vT_hi);
    cudaGetSymbolAddress((void**)&cxhi,  g_ctx_hi);

    static cudaStream_t s1 = nullptr;
    static cudaEvent_t evF = nullptr, evKV = nullptr, evO = nullptr;
    static int configured = 0;
    if (!configured) {
        cudaFuncSetAttribute(gemm_fp16<true>,
            cudaFuncAttributeMaxDynamicSharedMemorySize, GSMEM);
        cudaFuncSetAttribute(gemm_fp16<false>,
            cudaFuncAttributeMaxDynamicSharedMemorySize, GSMEM);
        cudaFuncSetAttribute(flash_attn,
            cudaFuncAttributeMaxDynamicSharedMemorySize, FA_SMEM);
        cudaStreamCreateWithFlags(&s1, cudaStreamNonBlocking);
        cudaEventCreateWithFlags(&evF, cudaEventDisableTiming);
        cudaEventCreateWithFlags(&evKV, cudaEventDisableTiming);
        cudaEventCreateWithFlags(&evO, cudaEventDisableTiming);
        configured = 1;
    }

    dim3 blk(256);

    // 0a) stream0: hs convert, then FORK s1 off the capture stream.
    cvt_kernel<<<1024, 256>>>((const float4*)hs, (uint2*)hshi, S * HID / 4);
    cudaEventRecord(evF, 0);
    cudaStreamWaitEvent(s1, evF, 0);

    // 0b) stream1: Wk, Wv (needed by QKV GEMM, join evKV), then Wo
    cvt_kernel<<<1024, 256, 0, s1>>>((const float4*)Wk,
        (uint2*)(wqkvhi + (size_t)HID * HID), KVHID * HID / 4);
    cvt_kernel<<<1024, 256, 0, s1>>>((const float4*)Wv,
        (uint2*)(wqkvhi + (size_t)(HID + KVHID) * HID), KVHID * HID / 4);
    cudaEventRecord(evKV, s1);
    cvt_kernel<<<1024, 256, 0, s1>>>((const float4*)Wo, (uint2*)wohi,
                                     HID * HID / 4);
    cudaEventRecord(evO, s1);

    // 0c) stream0: Wq convert (largest of the GEMM inputs)
    cvt_kernel<<<1024, 256>>>((const float4*)Wq, (uint2*)wqkvhi, HID * HID / 4);

    // 1) merged projection GEMM (joins Wk/Wv from s1)
    cudaStreamWaitEvent(0, evKV, 0);
    gemm_fp16<true><<<dim3(QKVW / 128, S / 128), blk, GSMEM>>>(
        hshi, wqkvhi, nullptr, HID, HID, HID, 0,
        pos, prior, qhi, khi, vthi);

    // 2) fused flash attention -> ctx fp16 (Wo cvt finishing on s1)
    flash_attn<<<dim3(H, S / 128), blk, FA_SMEM>>>(
        qhi, khi, vthi, prior, m1, m2, cxhi);

    // 3) out = ctx @ Wo^T, gated on Wo conversion (join s1 back into capture)
    cudaStreamWaitEvent(0, evO, 0);
    gemm_fp16<false><<<dim3(HID / 128, S / 128), blk, GSMEM>>>(
        cxhi, wohi, out, HID, HID, HID, HID,
        nullptr, nullptr, nullptr, nullptr, nullptr);
}